// round 1
// baseline (speedup 1.0000x reference)
#include <cuda_runtime.h>
#include <math.h>

#define H_ 224
#define W_ 224
#define HW 50176
#define NF 4
#define NSAMP 4096
#define EPSF 1e-6f

// ------------------------- device scratch (no allocations) -------------------------
__device__ float    g_scale[NF];
__device__ float    g_mask_frame[NF];
__device__ double   g_sum_absdiff;
__device__ double   g_sum_normal;
__device__ double   g_pose_loss;
__device__ float    g_relgt[NF][12];      // rot row-major 9 + trans 3
__device__ unsigned g_medkeys[NF * HW];
__device__ unsigned g_selT[NF];
__device__ int      g_selcount[NF];
__device__ float4   g_ps[NF][NSAMP];      // pred point xyz + 0.5*|p|^2
__device__ float4   g_gs[NF][NSAMP];      // gt   point xyz + 0.5*|g|^2
__device__ float    g_w[NF][NSAMP];       // mask at selected sample
__device__ float    g_wsel[NF];
__device__ double   g_cd_sum[NF];

// ------------------------- helpers -------------------------
__device__ __forceinline__ float blockReduceSum(float v, float* sh) {
    int lane = threadIdx.x & 31, wid = threadIdx.x >> 5;
#pragma unroll
    for (int o = 16; o; o >>= 1) v += __shfl_down_sync(0xffffffffu, v, o);
    if (lane == 0) sh[wid] = v;
    __syncthreads();
    int nw = (blockDim.x + 31) >> 5;
    v = (threadIdx.x < nw) ? sh[threadIdx.x] : 0.f;
    if (wid == 0) {
#pragma unroll
        for (int o = 16; o; o >>= 1) v += __shfl_down_sync(0xffffffffu, v, o);
    }
    return v;
}

__device__ void inv4(const float* m, float* inv) {
    float a[4][8];
    for (int i = 0; i < 4; i++)
        for (int j = 0; j < 4; j++) { a[i][j] = m[i * 4 + j]; a[i][j + 4] = (i == j) ? 1.f : 0.f; }
    for (int c = 0; c < 4; c++) {
        int piv = c; float best = fabsf(a[c][c]);
        for (int r = c + 1; r < 4; r++) { float v = fabsf(a[r][c]); if (v > best) { best = v; piv = r; } }
        if (piv != c)
            for (int j = 0; j < 8; j++) { float t = a[c][j]; a[c][j] = a[piv][j]; a[piv][j] = t; }
        float id = 1.f / a[c][c];
        for (int j = 0; j < 8; j++) a[c][j] *= id;
        for (int r = 0; r < 4; r++) {
            if (r == c) continue;
            float fm = a[r][c];
            for (int j = 0; j < 8; j++) a[r][j] -= fm * a[c][j];
        }
    }
    for (int i = 0; i < 4; i++)
        for (int j = 0; j < 4; j++) inv[i * 4 + j] = a[i][j + 4];
}

__device__ void mm4(const float* A, const float* B, float* C) {
    for (int i = 0; i < 4; i++)
        for (int j = 0; j < 4; j++) {
            float s = 0.f;
            for (int k = 0; k < 4; k++) s += A[i * 4 + k] * B[k * 4 + j];
            C[i * 4 + j] = s;
        }
}

// normal at interior pixel from 4 neighbor depths; returns normalized (or zero) vector
__device__ __forceinline__ void compnorm(int x, int y,
                                         float dL, float dR, float dU, float dD,
                                         float cx, float cy, float ifx, float ify,
                                         float* out) {
    // cam point: X=(xx-cx)*ifx*d, Y=(yy-cy)*ify*d, Z=d
    float Rx = ((float)(x + 1) - cx) * ifx * dR, Ry = ((float)y - cy) * ify * dR, Rz = dR;
    float Lx = ((float)(x - 1) - cx) * ifx * dL, Ly = ((float)y - cy) * ify * dL, Lz = dL;
    float Dx = ((float)x - cx) * ifx * dD, Dy = ((float)(y + 1) - cy) * ify * dD, Dz = dD;
    float Ux = ((float)x - cx) * ifx * dU, Uy = ((float)(y - 1) - cy) * ify * dU, Uz = dU;
    float bx = Rx - Lx, by = Ry - Ly, bz = Rz - Lz;   // fx_diff
    float ax = Dx - Ux, ay = Dy - Uy, az = Dz - Uz;   // fy_diff
    float c0 = ay * bz - az * by;
    float c1 = az * bx - ax * bz;
    float c2 = ax * by - ay * bx;
    float n = sqrtf(c0 * c0 + c1 * c1 + c2 * c2);
    float iv = 1.f / fmaxf(n, EPSF);
    out[0] = c0 * iv; out[1] = c1 * iv; out[2] = c2 * iv;
}

// ------------------------- kernels -------------------------
__global__ void k_init() {
    int i = blockIdx.x * blockDim.x + threadIdx.x;
    if (i == 0) { g_sum_absdiff = 0.0; g_sum_normal = 0.0; g_pose_loss = 0.0; }
    if (i < NF) { g_mask_frame[i] = 0.f; g_selcount[i] = 0; g_wsel[i] = 0.f; g_cd_sum[i] = 0.0; }
    // defensive preset of sample buffers (exactly 4096 slots get overwritten per frame)
    for (int t = i; t < NF * NSAMP; t += gridDim.x * blockDim.x) {
        int f = t / NSAMP, s = t - f * NSAMP;
        g_ps[f][s] = make_float4(1e9f, 1e9f, 1e9f, 1.5e18f);
        g_gs[f][s] = make_float4(1e9f, 1e9f, 1e9f, 1.5e18f);
        g_w[f][s] = 0.f;
    }
}

__global__ void k_pose(const float* pp, const float* pg) {
    if (threadIdx.x == 0 && blockIdx.x == 0) {
        float ip[16], ig[16];
        inv4(pp, ip);
        inv4(pg, ig);
        double acc = 0.0;
        for (int s = 0; s < NF; s++) {
            float rp[16], rg[16];
            mm4(ip, pp + s * 16, rp);
            mm4(ig, pg + s * 16, rg);
            for (int k = 0; k < 16; k++) acc += (double)fabsf(rp[k] - rg[k]);
            g_relgt[s][0] = rg[0];  g_relgt[s][1] = rg[1];  g_relgt[s][2] = rg[2];
            g_relgt[s][3] = rg[4];  g_relgt[s][4] = rg[5];  g_relgt[s][5] = rg[6];
            g_relgt[s][6] = rg[8];  g_relgt[s][7] = rg[9];  g_relgt[s][8] = rg[10];
            g_relgt[s][9] = rg[3];  g_relgt[s][10] = rg[7]; g_relgt[s][11] = rg[11];
        }
        g_pose_loss = acc / 64.0;
    }
}

__global__ void k_medkeys(const float* dp, const float* dg) {
    int i = blockIdx.x * blockDim.x + threadIdx.x;
    if (i < NF * HW) {
        float dgv = dg[i], dpv = dp[i];
        bool m = (dgv > 0.f) && isfinite(dgv) && (dgv > 1e-6f) && isfinite(dpv) && (dpv > 1e-6f);
        unsigned key = 0u;
        if (m) {
            float r = dpv / fmaxf(dgv, EPSF);
            unsigned u = __float_as_uint(r);
            key = (u & 0x80000000u) ? ~u : (u | 0x80000000u);
            if (key == 0u) key = 1u;
        }
        g_medkeys[i] = key;
    }
}

// one block per frame: exact nanmedian via 3-level MSD radix select (11/11/10 bits)
__global__ void k_median() {
    int f = blockIdx.x;
    const unsigned* keys = g_medkeys + (size_t)f * HW;
    __shared__ unsigned hist[2048];
    __shared__ unsigned hist0[2048];
    __shared__ unsigned s_cnt, s_pref, s_rank;
    if (threadIdx.x == 0) s_cnt = 0;
    for (int i = threadIdx.x; i < 2048; i += blockDim.x) hist[i] = 0;
    __syncthreads();
    for (int i = threadIdx.x; i < HW; i += blockDim.x) {
        unsigned k = keys[i];
        if (k) atomicAdd(&hist[k >> 21], 1u);
    }
    __syncthreads();
    unsigned c = 0;
    for (int i = threadIdx.x; i < 2048; i += blockDim.x) { hist0[i] = hist[i]; c += hist[i]; }
    atomicAdd(&s_cnt, c);
    __syncthreads();
    unsigned cnt = s_cnt;
    if (cnt < 16) {
        if (threadIdx.x == 0) g_scale[f] = 1.f;
        return;
    }
    unsigned ranks[2]; int nr;
    if (cnt & 1u) { ranks[0] = cnt >> 1; ranks[1] = cnt >> 1; nr = 1; }
    else { ranks[0] = (cnt >> 1) - 1u; ranks[1] = cnt >> 1; nr = 2; }
    float vals[2];
    for (int q = 0; q < 2; q++) {
        if (q == 1 && nr == 1) { vals[1] = vals[0]; break; }
        unsigned rank = ranks[q];
        if (threadIdx.x == 0) {
            unsigned cum = 0, b = 0;
            for (; b < 2048; b++) { unsigned hc = hist0[b]; if (cum + hc > rank) break; cum += hc; }
            s_pref = b; s_rank = rank - cum;
        }
        __syncthreads();
        unsigned p0 = s_pref;
        for (int i = threadIdx.x; i < 2048; i += blockDim.x) hist[i] = 0;
        __syncthreads();
        for (int i = threadIdx.x; i < HW; i += blockDim.x) {
            unsigned k = keys[i];
            if (k && (k >> 21) == p0) atomicAdd(&hist[(k >> 10) & 2047u], 1u);
        }
        __syncthreads();
        if (threadIdx.x == 0) {
            unsigned rk = s_rank, cum = 0, b = 0;
            for (; b < 2048; b++) { unsigned hc = hist[b]; if (cum + hc > rk) break; cum += hc; }
            s_pref = (p0 << 11) | b; s_rank = rk - cum;
        }
        __syncthreads();
        unsigned p01 = s_pref;
        for (int i = threadIdx.x; i < 1024; i += blockDim.x) hist[i] = 0;
        __syncthreads();
        for (int i = threadIdx.x; i < HW; i += blockDim.x) {
            unsigned k = keys[i];
            if (k && (k >> 10) == p01) atomicAdd(&hist[k & 1023u], 1u);
        }
        __syncthreads();
        if (threadIdx.x == 0) {
            unsigned rk = s_rank, cum = 0, b = 0;
            for (; b < 1024; b++) { unsigned hc = hist[b]; if (cum + hc > rk) break; cum += hc; }
            s_pref = (p01 << 10) | b;
        }
        __syncthreads();
        unsigned kk = s_pref;
        unsigned bits = (kk & 0x80000000u) ? (kk ^ 0x80000000u) : ~kk;
        vals[q] = __uint_as_float(bits);
        __syncthreads();
    }
    if (threadIdx.x == 0) {
        float med = (nr == 2) ? 0.5f * (vals[0] + vals[1]) : vals[0];
        float sc = (!isfinite(med)) ? 1.f : fminf(fmaxf(med, 1e-3f), 1e3f);
        g_scale[f] = sc;
    }
}

// per-pixel: mask count, depth L1, normal cosine term
__global__ void k_perpixel(const float* dp_, const float* dg_, const float* intr) {
    __shared__ float sh[32];
    int f = blockIdx.y;
    int p = blockIdx.x * blockDim.x + threadIdx.x;
    float mterm = 0.f, l1 = 0.f, nterm = 0.f;
    if (p < HW) {
        const float* dp = dp_ + (size_t)f * HW;
        const float* dg = dg_ + (size_t)f * HW;
        float fx = fmaxf(intr[f * 9 + 0], EPSF), fy = fmaxf(intr[f * 9 + 4], EPSF);
        float cx = intr[f * 9 + 2], cy = intr[f * 9 + 5];
        float ifx = 1.f / fx, ify = 1.f / fy;
        int y = p / W_, x = p - y * W_;
        float dgv = dg[p], dpv = dp[p];
        bool mask = (dgv > 0.f) && isfinite(dgv) && (dgv > 1e-6f);
        float sc = g_scale[f];
        mterm = mask ? 1.f : 0.f;
        l1 = fabsf(dpv - dgv * sc) * mterm;
        float cosv = 0.f;
        if (x > 0 && x < W_ - 1 && y > 0 && y < H_ - 1) {
            float pL = dp[p - 1], pR = dp[p + 1], pU = dp[p - W_], pD = dp[p + W_];
            float gL = dg[p - 1] * sc, gR = dg[p + 1] * sc, gU = dg[p - W_] * sc, gD = dg[p + W_] * sc;
            float n1[3], n2[3];
            compnorm(x, y, pL, pR, pU, pD, cx, cy, ifx, ify, n1);
            compnorm(x, y, gL, gR, gU, gD, cx, cy, ifx, ify, n2);
            float d = n1[0] * n2[0] + n1[1] * n2[1] + n1[2] * n2[2];
            cosv = fminf(fmaxf(d, -1.f), 1.f);
        }
        nterm = (1.f - cosv) * mterm;
    }
    float s;
    s = blockReduceSum(mterm, sh);
    if (threadIdx.x == 0) atomicAdd(&g_mask_frame[f], s);
    __syncthreads();
    s = blockReduceSum(l1, sh);
    if (threadIdx.x == 0) atomicAdd(&g_sum_absdiff, (double)s);
    __syncthreads();
    s = blockReduceSum(nterm, sh);
    if (threadIdx.x == 0) atomicAdd(&g_sum_normal, (double)s);
}

// top-4096 threshold over 21-bit keys (mask<<20 | hash); keys are all distinct
__global__ void k_sel_thresh(const float* dg_) {
    int f = blockIdx.x;
    const float* dg = dg_ + (size_t)f * HW;
    __shared__ unsigned hist[2048];
    __shared__ unsigned s_bin, s_need;
    for (int i = threadIdx.x; i < 2048; i += blockDim.x) hist[i] = 0;
    __syncthreads();
    for (int p = threadIdx.x; p < HW; p += blockDim.x) {
        float dgv = dg[p];
        bool m = (dgv > 0.f) && isfinite(dgv) && (dgv > 1e-6f);
        unsigned key = (((unsigned)p * 2654435761u) & 0xFFFFFu) | (m ? (1u << 20) : 0u);
        atomicAdd(&hist[key >> 10], 1u);
    }
    __syncthreads();
    if (threadIdx.x == 0) {
        unsigned c = 0; int b;
        for (b = 2047; b >= 0; b--) { c += hist[b]; if (c >= NSAMP) break; }
        s_bin = (unsigned)b; s_need = NSAMP - (c - hist[b]);
    }
    __syncthreads();
    unsigned bin = s_bin, need = s_need;
    for (int i = threadIdx.x; i < 1024; i += blockDim.x) hist[i] = 0;
    __syncthreads();
    for (int p = threadIdx.x; p < HW; p += blockDim.x) {
        float dgv = dg[p];
        bool m = (dgv > 0.f) && isfinite(dgv) && (dgv > 1e-6f);
        unsigned key = (((unsigned)p * 2654435761u) & 0xFFFFFu) | (m ? (1u << 20) : 0u);
        if ((key >> 10) == bin) atomicAdd(&hist[key & 1023u], 1u);
    }
    __syncthreads();
    if (threadIdx.x == 0) {
        unsigned c = 0; int l;
        for (l = 1023; l >= 0; l--) { c += hist[l]; if (c >= need) break; }
        g_selT[f] = (bin << 10) | (unsigned)l;
    }
}

// compact selected samples; compute gt world point and packed half-norms
__global__ void k_gather(const float* dg_, const float* ppts, const float* intr) {
    int f = blockIdx.y;
    unsigned T = g_selT[f];
    const float* dg = dg_ + (size_t)f * HW;
    float sc = g_scale[f];
    float fx = fmaxf(intr[f * 9 + 0], EPSF), fy = fmaxf(intr[f * 9 + 4], EPSF);
    float cx = intr[f * 9 + 2], cy = intr[f * 9 + 5];
    float ifx = 1.f / fx, ify = 1.f / fy;
    float r00 = g_relgt[f][0], r01 = g_relgt[f][1], r02 = g_relgt[f][2];
    float r10 = g_relgt[f][3], r11 = g_relgt[f][4], r12 = g_relgt[f][5];
    float r20 = g_relgt[f][6], r21 = g_relgt[f][7], r22 = g_relgt[f][8];
    float t0 = g_relgt[f][9], t1 = g_relgt[f][10], t2 = g_relgt[f][11];

    int p = blockIdx.x * blockDim.x + threadIdx.x;
    if (p < HW) {
        unsigned h = ((unsigned)p * 2654435761u) & 0xFFFFFu;
        float dgv = dg[p];
        bool mask = (dgv > 0.f) && isfinite(dgv) && (dgv > 1e-6f);
        unsigned key = h | (mask ? (1u << 20) : 0u);
        if (key >= T) {
            int slot = atomicAdd(&g_selcount[f], 1);
            if (slot < NSAMP) {
                float w = mask ? 1.f : 0.f;
                const float* pp = ppts + ((size_t)f * HW + p) * 3;
                float px = pp[0], py = pp[1], pz = pp[2];
                if (!mask) { px = 1e9f; py = 1e9f; pz = 1e9f; }
                g_ps[f][slot] = make_float4(px, py, pz, 0.5f * (px * px + py * py + pz * pz));
                int y = p / W_, x = p - y * W_;
                float dgal = dgv * sc;
                float X = ((float)x - cx) * ifx * dgal;
                float Y = ((float)y - cy) * ify * dgal;
                float Z = dgal;
                float gx = r00 * X + r01 * Y + r02 * Z + t0;
                float gy = r10 * X + r11 * Y + r12 * Z + t1;
                float gz = r20 * X + r21 * Y + r22 * Z + t2;
                if (!mask) { gx = 1e9f; gy = 1e9f; gz = 1e9f; }
                g_gs[f][slot] = make_float4(gx, gy, gz, 0.5f * (gx * gx + gy * gy + gz * gz));
                g_w[f][slot] = w;
                if (mask) atomicAdd(&g_wsel[f], 1.f);
            }
        }
    }
}

// chamfer: blockIdx.z = direction (0: rows=pred over gt, 1: rows=gt over pred)
__global__ void __launch_bounds__(128, 8) k_chamfer() {
    __shared__ float4 sb[256];
    __shared__ float shr[32];
    int f = blockIdx.y;
    int dir = blockIdx.z;
    int r = blockIdx.x * 128 + threadIdx.x;
    const float4* A = dir ? g_gs[f] : g_ps[f];
    const float4* B = dir ? g_ps[f] : g_gs[f];
    float4 a = A[r];
    float ax = a.x, ay = a.y, az = a.z, aw = a.w;
    float rm0 = 3.0e38f, rm1 = 3.0e38f, rm2 = 3.0e38f, rm3 = 3.0e38f;
    for (int t = 0; t < NSAMP; t += 256) {
        __syncthreads();
        sb[threadIdx.x] = B[t + threadIdx.x];
        sb[threadIdx.x + 128] = B[t + threadIdx.x + 128];
        __syncthreads();
#pragma unroll 8
        for (int j = 0; j < 256; j += 4) {
            float4 b0 = sb[j], b1 = sb[j + 1], b2 = sb[j + 2], b3 = sb[j + 3];
            float u0 = fmaf(-ax, b0.x, b0.w); u0 = fmaf(-ay, b0.y, u0); u0 = fmaf(-az, b0.z, u0);
            float u1 = fmaf(-ax, b1.x, b1.w); u1 = fmaf(-ay, b1.y, u1); u1 = fmaf(-az, b1.z, u1);
            float u2 = fmaf(-ax, b2.x, b2.w); u2 = fmaf(-ay, b2.y, u2); u2 = fmaf(-az, b2.z, u2);
            float u3 = fmaf(-ax, b3.x, b3.w); u3 = fmaf(-ay, b3.y, u3); u3 = fmaf(-az, b3.z, u3);
            rm0 = fminf(rm0, u0); rm1 = fminf(rm1, u1);
            rm2 = fminf(rm2, u2); rm3 = fminf(rm3, u3);
        }
    }
    float rmin = fminf(fminf(rm0, rm1), fminf(rm2, rm3));
    float d2 = 2.f * (rmin + aw);
    float d = fminf(sqrtf(fmaxf(d2, 1e-12f)), 1e9f);
    float contrib = d * g_w[f][r];
    __syncthreads();
    float s = blockReduceSum(contrib, shr);
    if (threadIdx.x == 0) atomicAdd(&g_cd_sum[f], (double)s);
}

__global__ void k_final(float* out) {
    if (threadIdx.x == 0 && blockIdx.x == 0) {
        double wsum = 0.0;
        for (int f = 0; f < NF; f++) wsum += (double)g_mask_frame[f];
        double denom = (wsum > 1.0) ? wsum : 1.0;
        double depth_loss = g_sum_absdiff / denom;
        double normal_loss = g_sum_normal / denom;
        double cds = 0.0, oks = 0.0;
        for (int f = 0; f < NF; f++) {
            double ws = (double)g_wsel[f];
            double dn = (ws > 1.0) ? ws : 1.0;
            double cd = g_cd_sum[f] / dn;
            if (g_mask_frame[f] >= 10.f) { cds += cd; oks += 1.0; }
        }
        double points_loss = cds / ((oks > 1.0) ? oks : 1.0);
        out[0] = (float)(g_pose_loss + depth_loss + points_loss + normal_loss);
    }
}

// ------------------------- launcher -------------------------
extern "C" void kernel_launch(void* const* d_in, const int* in_sizes, int n_in,
                              void* d_out, int out_size) {
    const float* depth_pred = (const float*)d_in[0];
    const float* points_pred = (const float*)d_in[1];
    const float* depth_gt = (const float*)d_in[2];
    const float* intrinsics = (const float*)d_in[3];
    const float* pose_pred = (const float*)d_in[4];
    const float* pose_gt = (const float*)d_in[5];
    float* out = (float*)d_out;

    k_init<<<64, 256>>>();
    k_pose<<<1, 32>>>(pose_pred, pose_gt);
    k_medkeys<<<(NF * HW + 255) / 256, 256>>>(depth_pred, depth_gt);
    k_median<<<NF, 1024>>>();
    k_perpixel<<<dim3(HW / 256, NF), 256>>>(depth_pred, depth_gt, intrinsics);
    k_sel_thresh<<<NF, 1024>>>(depth_gt);
    k_gather<<<dim3(HW / 256, NF), 256>>>(depth_gt, points_pred, intrinsics);
    k_chamfer<<<dim3(NSAMP / 128, NF, 2), 128>>>();
    k_final<<<1, 32>>>(out);
}

// round 2
// speedup vs baseline: 2.0035x; 2.0035x over previous
#include <cuda_runtime.h>
#include <math.h>

#define H_ 224
#define W_ 224
#define HW 50176
#define NF 4
#define NSAMP 4096
#define EPSF 1e-6f

// ------------------------- device scratch (no allocations) -------------------------
__device__ float    g_scale[NF];
__device__ float    g_mask_frame[NF];
__device__ double   g_sum_absdiff;
__device__ double   g_sum_normal;
__device__ double   g_pose_loss;
__device__ float    g_relgt[NF][12];
__device__ unsigned g_medkeys[NF * HW];
__device__ unsigned g_maskbits[NF][HW / 32];
__device__ unsigned g_h0[NF][2048];
__device__ unsigned g_h1[NF][2][2048];
__device__ unsigned g_h2[NF][2][1024];
__device__ unsigned g_sh0[NF][2048];
__device__ unsigned g_sh1[NF][1024];
__device__ unsigned g_pref0[NF][2];
__device__ unsigned g_rank1[NF][2];
__device__ unsigned g_pref1[NF][2];
__device__ unsigned g_rank2[NF][2];
__device__ int      g_lowcnt[NF];
__device__ unsigned g_selbin[NF];
__device__ unsigned g_selneed[NF];
__device__ unsigned g_selT[NF];
__device__ int      g_selcount[NF];
__device__ float4   g_ps[NF][NSAMP];   // pred point xyz + 0.5*|p|^2
__device__ float4   g_gs[NF][NSAMP];   // gt   point xyz + 0.5*|g|^2
__device__ float    g_w[NF][NSAMP];
__device__ float    g_wsel[NF];
__device__ unsigned g_rowmin[2][NF][NSAMP];

// ------------------------- helpers -------------------------
__device__ __forceinline__ float blockReduceSum(float v, float* sh) {
    int lane = threadIdx.x & 31, wid = threadIdx.x >> 5;
#pragma unroll
    for (int o = 16; o; o >>= 1) v += __shfl_down_sync(0xffffffffu, v, o);
    if (lane == 0) sh[wid] = v;
    __syncthreads();
    int nw = (blockDim.x + 31) >> 5;
    v = (threadIdx.x < nw) ? sh[threadIdx.x] : 0.f;
    if (wid == 0) {
#pragma unroll
        for (int o = 16; o; o >>= 1) v += __shfl_down_sync(0xffffffffu, v, o);
    }
    return v;
}

// block = 1024 threads. Each thread owns bins (2t, 2t+1). Returns total; excl =
// exclusive prefix before bin 2t.
__device__ __forceinline__ unsigned blockScanPair(unsigned a0, unsigned a1,
                                                  unsigned* ws, unsigned& excl) {
    __syncthreads();
    unsigned lane = threadIdx.x & 31, wid = threadIdx.x >> 5;
    unsigned s = a0 + a1, v = s;
#pragma unroll
    for (int o = 1; o < 32; o <<= 1) { unsigned t = __shfl_up_sync(0xffffffffu, v, o); if (lane >= o) v += t; }
    if (lane == 31) ws[wid] = v;
    __syncthreads();
    if (wid == 0) {
        unsigned w = ws[lane];
#pragma unroll
        for (int o = 1; o < 32; o <<= 1) { unsigned t = __shfl_up_sync(0xffffffffu, w, o); if (lane >= o) w += t; }
        ws[lane] = w;
    }
    __syncthreads();
    unsigned warpoff = wid ? ws[wid - 1] : 0u;
    excl = warpoff + v - s;
    return ws[31];
}

__device__ __forceinline__ unsigned f2key(float v) {
    unsigned b = __float_as_uint(v);
    return (b & 0x80000000u) ? ~b : (b | 0x80000000u);
}
__device__ __forceinline__ float key2f(unsigned k) {
    unsigned b = (k & 0x80000000u) ? (k ^ 0x80000000u) : ~k;
    return __uint_as_float(b);
}

__device__ __forceinline__ unsigned long long pk2(float lo, float hi) {
    unsigned long long u;
    asm("mov.b64 %0,{%1,%2};" : "=l"(u) : "f"(lo), "f"(hi));
    return u;
}
__device__ __forceinline__ void upk2(unsigned long long u, float& lo, float& hi) {
    asm("mov.b64 {%0,%1},%2;" : "=f"(lo), "=f"(hi) : "l"(u));
}
__device__ __forceinline__ unsigned long long fma2(unsigned long long a,
                                                   unsigned long long b,
                                                   unsigned long long c) {
    unsigned long long d;
    asm("fma.rn.f32x2 %0,%1,%2,%3;" : "=l"(d) : "l"(a), "l"(b), "l"(c));
    return d;
}

// straight-line adjugate 4x4 inverse (row-major)
__device__ void inv4(const float* m, float* inv) {
    float s0 = m[0] * m[5] - m[4] * m[1];
    float s1 = m[0] * m[6] - m[4] * m[2];
    float s2 = m[0] * m[7] - m[4] * m[3];
    float s3 = m[1] * m[6] - m[5] * m[2];
    float s4 = m[1] * m[7] - m[5] * m[3];
    float s5 = m[2] * m[7] - m[6] * m[3];
    float c5 = m[10] * m[15] - m[14] * m[11];
    float c4 = m[9] * m[15] - m[13] * m[11];
    float c3 = m[9] * m[14] - m[13] * m[10];
    float c2 = m[8] * m[15] - m[12] * m[11];
    float c1 = m[8] * m[14] - m[12] * m[10];
    float c0 = m[8] * m[13] - m[12] * m[9];
    float det = s0 * c5 - s1 * c4 + s2 * c3 + s3 * c2 - s4 * c1 + s5 * c0;
    float id = 1.f / det;
    inv[0]  = ( m[5] * c5 - m[6] * c4 + m[7] * c3) * id;
    inv[1]  = (-m[1] * c5 + m[2] * c4 - m[3] * c3) * id;
    inv[2]  = ( m[13] * s5 - m[14] * s4 + m[15] * s3) * id;
    inv[3]  = (-m[9] * s5 + m[10] * s4 - m[11] * s3) * id;
    inv[4]  = (-m[4] * c5 + m[6] * c2 - m[7] * c1) * id;
    inv[5]  = ( m[0] * c5 - m[2] * c2 + m[3] * c1) * id;
    inv[6]  = (-m[12] * s5 + m[14] * s2 - m[15] * s1) * id;
    inv[7]  = ( m[8] * s5 - m[10] * s2 + m[11] * s1) * id;
    inv[8]  = ( m[4] * c4 - m[5] * c2 + m[7] * c0) * id;
    inv[9]  = (-m[0] * c4 + m[1] * c2 - m[3] * c0) * id;
    inv[10] = ( m[12] * s4 - m[13] * s2 + m[15] * s0) * id;
    inv[11] = (-m[8] * s4 + m[9] * s2 - m[11] * s0) * id;
    inv[12] = (-m[4] * c3 + m[5] * c1 - m[6] * c0) * id;
    inv[13] = ( m[0] * c3 - m[1] * c1 + m[2] * c0) * id;
    inv[14] = (-m[12] * s3 + m[13] * s1 - m[14] * s0) * id;
    inv[15] = ( m[8] * s3 - m[9] * s1 + m[10] * s0) * id;
}

__device__ void mm4(const float* A, const float* B, float* C) {
    for (int i = 0; i < 4; i++)
        for (int j = 0; j < 4; j++) {
            float s = 0.f;
            for (int k = 0; k < 4; k++) s += A[i * 4 + k] * B[k * 4 + j];
            C[i * 4 + j] = s;
        }
}

__device__ __forceinline__ void compnorm(int x, int y,
                                         float dL, float dR, float dU, float dD,
                                         float cx, float cy, float ifx, float ify,
                                         float* out) {
    float Rx = ((float)(x + 1) - cx) * ifx * dR, Ry = ((float)y - cy) * ify * dR, Rz = dR;
    float Lx = ((float)(x - 1) - cx) * ifx * dL, Ly = ((float)y - cy) * ify * dL, Lz = dL;
    float Dx = ((float)x - cx) * ifx * dD, Dy = ((float)(y + 1) - cy) * ify * dD, Dz = dD;
    float Ux = ((float)x - cx) * ifx * dU, Uy = ((float)(y - 1) - cy) * ify * dU, Uz = dU;
    float bx = Rx - Lx, by = Ry - Ly, bz = Rz - Lz;
    float ax = Dx - Ux, ay = Dy - Uy, az = Dz - Uz;
    float c0 = ay * bz - az * by;
    float c1 = az * bx - ax * bz;
    float c2 = ax * by - ay * bx;
    float n = sqrtf(c0 * c0 + c1 * c1 + c2 * c2);
    float iv = 1.f / fmaxf(n, EPSF);
    out[0] = c0 * iv; out[1] = c1 * iv; out[2] = c2 * iv;
}

// ------------------------- kernels -------------------------
__global__ void k_init() {
    int i = blockIdx.x * blockDim.x + threadIdx.x;
    int stride = gridDim.x * blockDim.x;
    if (i == 0) { g_sum_absdiff = 0.0; g_sum_normal = 0.0; g_pose_loss = 0.0; }
    if (i < NF) {
        g_mask_frame[i] = 0.f; g_selcount[i] = 0; g_wsel[i] = 0.f;
        g_lowcnt[i] = 0; g_selbin[i] = 0; g_selneed[i] = 1; g_selT[i] = 0;
        g_pref0[i][0] = g_pref0[i][1] = 0; g_rank1[i][0] = g_rank1[i][1] = 0;
        g_pref1[i][0] = g_pref1[i][1] = 0; g_rank2[i][0] = g_rank2[i][1] = 0;
    }
    for (int t = i; t < NF * 2048; t += stride) { ((unsigned*)g_h0)[t] = 0; ((unsigned*)g_sh0)[t] = 0; }
    for (int t = i; t < NF * 2 * 2048; t += stride) ((unsigned*)g_h1)[t] = 0;
    for (int t = i; t < NF * 2 * 1024; t += stride) ((unsigned*)g_h2)[t] = 0;
    for (int t = i; t < NF * 1024; t += stride) ((unsigned*)g_sh1)[t] = 0;
    for (int t = i; t < 2 * NF * NSAMP; t += stride) ((unsigned*)g_rowmin)[t] = 0xFFFFFFFFu;
    for (int t = i; t < NF * NSAMP; t += stride) {
        int f = t >> 12, s = t & (NSAMP - 1);
        g_ps[f][s] = make_float4(1e9f, 1e9f, 1e9f, 1.5e18f);
        g_gs[f][s] = make_float4(1e9f, 1e9f, 1e9f, 1.5e18f);
        g_w[f][s] = 0.f;
    }
}

__global__ void k_pose(const float* pp, const float* pg) {
    if (threadIdx.x == 0 && blockIdx.x == 0) {
        float ip[16], ig[16];
        inv4(pp, ip);
        inv4(pg, ig);
        double acc = 0.0;
        for (int s = 0; s < NF; s++) {
            float rp[16], rg[16];
            mm4(ip, pp + s * 16, rp);
            mm4(ig, pg + s * 16, rg);
            for (int k = 0; k < 16; k++) acc += (double)fabsf(rp[k] - rg[k]);
            g_relgt[s][0] = rg[0];  g_relgt[s][1] = rg[1];  g_relgt[s][2] = rg[2];
            g_relgt[s][3] = rg[4];  g_relgt[s][4] = rg[5];  g_relgt[s][5] = rg[6];
            g_relgt[s][6] = rg[8];  g_relgt[s][7] = rg[9];  g_relgt[s][8] = rg[10];
            g_relgt[s][9] = rg[3];  g_relgt[s][10] = rg[7]; g_relgt[s][11] = rg[11];
        }
        g_pose_loss = acc / 64.0;
    }
}

// full-chip: median keys + level-0 median hist (shared pre-agg) + sel level-0 hist
__global__ void k_pass1(const float* dp_, const float* dg_) {
    __shared__ unsigned sh[2048];
    int f = blockIdx.y;
    for (int i = threadIdx.x; i < 2048; i += 512) sh[i] = 0;
    __syncthreads();
    int p = blockIdx.x * 512 + threadIdx.x;
    float dgv = dg_[f * HW + p], dpv = dp_[f * HW + p];
    bool mk = (dgv > 0.f) && isfinite(dgv) && (dgv > 1e-6f);
    bool mm = mk && isfinite(dpv) && (dpv > 1e-6f);
    unsigned key = 0u;
    if (mm) {
        float r = dpv / fmaxf(dgv, EPSF);
        unsigned u = __float_as_uint(r);
        key = (u & 0x80000000u) ? ~u : (u | 0x80000000u);
        if (!key) key = 1u;
    }
    g_medkeys[f * HW + p] = key;
    if (key) atomicAdd(&sh[key >> 21], 1u);
    unsigned bal = __ballot_sync(0xffffffffu, mk);
    if ((threadIdx.x & 31) == 0) g_maskbits[f][p >> 5] = bal;
    unsigned sk = (((unsigned)p * 2654435761u) & 0xFFFFFu) | (mk ? (1u << 20) : 0u);
    atomicAdd(&g_sh0[f][sk >> 10], 1u);
    __syncthreads();
    for (int i = threadIdx.x; i < 2048; i += 512) {
        unsigned v = sh[i];
        if (v) atomicAdd(&g_h0[f][i], v);
    }
}

__global__ void k_scan1() {
    int f = blockIdx.x, t = threadIdx.x;
    __shared__ unsigned ws[32];
    unsigned a0 = g_h0[f][2 * t], a1 = g_h0[f][2 * t + 1];
    unsigned excl;
    unsigned total = blockScanPair(a0, a1, ws, excl);
    if (t == 0) g_lowcnt[f] = (total < 16) ? 1 : 0;
    if (total) {
        unsigned r0, r1;
        if (total & 1u) { r0 = total >> 1; r1 = r0; }
        else { r0 = (total >> 1) - 1u; r1 = total >> 1; }
        unsigned rks[2] = {r0, r1};
#pragma unroll
        for (int q = 0; q < 2; q++) {
            unsigned rk = rks[q];
            if (excl <= rk && rk < excl + a0) { g_pref0[f][q] = 2 * t; g_rank1[f][q] = rk - excl; }
            else if (excl + a0 <= rk && rk < excl + a0 + a1) { g_pref0[f][q] = 2 * t + 1; g_rank1[f][q] = rk - excl - a0; }
        }
    }
    unsigned b0 = g_sh0[f][2 * t], b1 = g_sh0[f][2 * t + 1];
    unsigned excl2;
    unsigned tot2 = blockScanPair(b0, b1, ws, excl2);
    unsigned rk = tot2 - NSAMP;
    if (excl2 <= rk && rk < excl2 + b0) { g_selbin[f] = 2 * t; g_selneed[f] = excl2 + b0 - rk; }
    else if (excl2 + b0 <= rk && rk < excl2 + b0 + b1) { g_selbin[f] = 2 * t + 1; g_selneed[f] = excl2 + b0 + b1 - rk; }
}

__global__ void k_pass2() {
    int f = blockIdx.y;
    int p = blockIdx.x * 512 + threadIdx.x;
    unsigned key = g_medkeys[f * HW + p];
    unsigned p0 = g_pref0[f][0], p1 = g_pref0[f][1];
    if (key) {
        unsigned top = key >> 21, mid = (key >> 10) & 2047u;
        if (top == p0) atomicAdd(&g_h1[f][0][mid], 1u);
        if (p1 != p0 && top == p1) atomicAdd(&g_h1[f][1][mid], 1u);
    }
    unsigned mk = (g_maskbits[f][p >> 5] >> (p & 31)) & 1u;
    unsigned sk = (((unsigned)p * 2654435761u) & 0xFFFFFu) | (mk << 20);
    if ((sk >> 10) == g_selbin[f]) atomicAdd(&g_sh1[f][sk & 1023u], 1u);
}

__global__ void k_scan2() {
    int f = blockIdx.x, t = threadIdx.x;
    __shared__ unsigned ws[32];
    bool eq = (g_pref0[f][0] == g_pref0[f][1]);
#pragma unroll
    for (int q = 0; q < 2; q++) {
        int src = (eq && q == 1) ? 0 : q;
        unsigned a0 = g_h1[f][src][2 * t], a1 = g_h1[f][src][2 * t + 1];
        unsigned excl;
        blockScanPair(a0, a1, ws, excl);
        unsigned rk = g_rank1[f][q];
        if (excl <= rk && rk < excl + a0) { g_pref1[f][q] = (g_pref0[f][q] << 11) | (unsigned)(2 * t); g_rank2[f][q] = rk - excl; }
        else if (excl + a0 <= rk && rk < excl + a0 + a1) { g_pref1[f][q] = (g_pref0[f][q] << 11) | (unsigned)(2 * t + 1); g_rank2[f][q] = rk - excl - a0; }
    }
    unsigned b0 = (t < 512) ? g_sh1[f][2 * t] : 0u;
    unsigned b1 = (t < 512) ? g_sh1[f][2 * t + 1] : 0u;
    unsigned excl2;
    unsigned tot = blockScanPair(b0, b1, ws, excl2);
    unsigned need = g_selneed[f];
    unsigned rk = tot - need;
    if (t < 512) {
        if (excl2 <= rk && rk < excl2 + b0) g_selT[f] = (g_selbin[f] << 10) | (unsigned)(2 * t);
        else if (excl2 + b0 <= rk && rk < excl2 + b0 + b1) g_selT[f] = (g_selbin[f] << 10) | (unsigned)(2 * t + 1);
    }
}

__global__ void k_pass3() {
    int f = blockIdx.y;
    int p = blockIdx.x * 512 + threadIdx.x;
    unsigned key = g_medkeys[f * HW + p];
    if (!key) return;
    unsigned hi = key >> 10;
    unsigned q0 = g_pref1[f][0], q1 = g_pref1[f][1];
    if (hi == q0) atomicAdd(&g_h2[f][0][key & 1023u], 1u);
    if (q1 != q0 && hi == q1) atomicAdd(&g_h2[f][1][key & 1023u], 1u);
}

__global__ void k_scan3() {
    int f = blockIdx.x, t = threadIdx.x;
    __shared__ unsigned ws[32];
    __shared__ float sval[2];
    if (t < 2) sval[t] = 0.f;
    bool eq = (g_pref1[f][0] == g_pref1[f][1]);
#pragma unroll
    for (int q = 0; q < 2; q++) {
        int src = (eq && q == 1) ? 0 : q;
        unsigned a0 = (t < 512) ? g_h2[f][src][2 * t] : 0u;
        unsigned a1 = (t < 512) ? g_h2[f][src][2 * t + 1] : 0u;
        unsigned excl;
        blockScanPair(a0, a1, ws, excl);
        unsigned rk = g_rank2[f][q];
        unsigned binf = 0xFFFFFFFFu;
        if (t < 512) {
            if (excl <= rk && rk < excl + a0) binf = 2 * t;
            else if (excl + a0 <= rk && rk < excl + a0 + a1) binf = 2 * t + 1;
        }
        if (binf != 0xFFFFFFFFu) sval[q] = key2f((g_pref1[f][q] << 10) | binf);
        __syncthreads();
    }
    if (t == 0) {
        float med = 0.5f * (sval[0] + sval[1]);
        float sc = (g_lowcnt[f] || !isfinite(med)) ? 1.f : fminf(fmaxf(med, 1e-3f), 1e3f);
        g_scale[f] = sc;
    }
}

// fused per-pixel loss terms + sample gather
__global__ void k_pixel(const float* dp_, const float* dg_, const float* intr,
                        const float* ppts) {
    __shared__ float sh[32];
    int f = blockIdx.y;
    int p = blockIdx.x * 256 + threadIdx.x;
    const float* dp = dp_ + (size_t)f * HW;
    const float* dg = dg_ + (size_t)f * HW;
    float fx = fmaxf(intr[f * 9 + 0], EPSF), fy = fmaxf(intr[f * 9 + 4], EPSF);
    float cx = intr[f * 9 + 2], cy = intr[f * 9 + 5];
    float ifx = 1.f / fx, ify = 1.f / fy;
    float sc = g_scale[f];
    int y = p / W_, x = p - y * W_;
    float dgv = dg[p], dpv = dp[p];
    bool mask = (dgv > 0.f) && isfinite(dgv) && (dgv > 1e-6f);
    float mterm = mask ? 1.f : 0.f;
    float l1 = fabsf(dpv - dgv * sc) * mterm;
    float cosv = 0.f;
    if (x > 0 && x < W_ - 1 && y > 0 && y < H_ - 1) {
        float pL = dp[p - 1], pR = dp[p + 1], pU = dp[p - W_], pD = dp[p + W_];
        float gL = dg[p - 1] * sc, gR = dg[p + 1] * sc, gU = dg[p - W_] * sc, gD = dg[p + W_] * sc;
        float n1[3], n2[3];
        compnorm(x, y, pL, pR, pU, pD, cx, cy, ifx, ify, n1);
        compnorm(x, y, gL, gR, gU, gD, cx, cy, ifx, ify, n2);
        float d = n1[0] * n2[0] + n1[1] * n2[1] + n1[2] * n2[2];
        cosv = fminf(fmaxf(d, -1.f), 1.f);
    }
    float nterm = (1.f - cosv) * mterm;

    // gather selected samples
    unsigned T = g_selT[f];
    unsigned sk = (((unsigned)p * 2654435761u) & 0xFFFFFu) | (mask ? (1u << 20) : 0u);
    if (sk >= T) {
        int slot = atomicAdd(&g_selcount[f], 1);
        if (slot < NSAMP) {
            float w = mask ? 1.f : 0.f;
            const float* pp = ppts + ((size_t)f * HW + p) * 3;
            float px = pp[0], py = pp[1], pz = pp[2];
            if (!mask) { px = 1e9f; py = 1e9f; pz = 1e9f; }
            g_ps[f][slot] = make_float4(px, py, pz, 0.5f * (px * px + py * py + pz * pz));
            float r00 = g_relgt[f][0], r01 = g_relgt[f][1], r02 = g_relgt[f][2];
            float r10 = g_relgt[f][3], r11 = g_relgt[f][4], r12 = g_relgt[f][5];
            float r20 = g_relgt[f][6], r21 = g_relgt[f][7], r22 = g_relgt[f][8];
            float t0 = g_relgt[f][9], t1 = g_relgt[f][10], t2 = g_relgt[f][11];
            float dgal = dgv * sc;
            float X = ((float)x - cx) * ifx * dgal;
            float Y = ((float)y - cy) * ify * dgal;
            float Z = dgal;
            float gx = r00 * X + r01 * Y + r02 * Z + t0;
            float gy = r10 * X + r11 * Y + r12 * Z + t1;
            float gz = r20 * X + r21 * Y + r22 * Z + t2;
            if (!mask) { gx = 1e9f; gy = 1e9f; gz = 1e9f; }
            g_gs[f][slot] = make_float4(gx, gy, gz, 0.5f * (gx * gx + gy * gy + gz * gz));
            g_w[f][slot] = w;
            if (mask) atomicAdd(&g_wsel[f], 1.f);
        }
    }

    float s;
    s = blockReduceSum(mterm, sh);
    if (threadIdx.x == 0) atomicAdd(&g_mask_frame[f], s);
    __syncthreads();
    s = blockReduceSum(l1, sh);
    if (threadIdx.x == 0) atomicAdd(&g_sum_absdiff, (double)s);
    __syncthreads();
    s = blockReduceSum(nterm, sh);
    if (threadIdx.x == 0) atomicAdd(&g_sum_normal, (double)s);
}

// chamfer: packed f32x2 FMA, 2 rows/thread, 2 column halves, per-row atomicMin
__global__ void __launch_bounds__(128) k_chamfer() {
    __shared__ ulonglong2 sA[128];   // (bx pair, by pair)
    __shared__ ulonglong2 sB[128];   // (bz pair, bw pair)
    int f = blockIdx.y;
    int dir = blockIdx.z & 1, ch = blockIdx.z >> 1;
    int r = blockIdx.x * 256 + threadIdx.x;
    const float4* A = dir ? g_gs[f] : g_ps[f];
    const float4* B = dir ? g_ps[f] : g_gs[f];
    float4 a0 = A[r], a1 = A[r + 128];
    unsigned long long nax0 = pk2(-a0.x, -a0.x), nay0 = pk2(-a0.y, -a0.y), naz0 = pk2(-a0.z, -a0.z);
    unsigned long long nax1 = pk2(-a1.x, -a1.x), nay1 = pk2(-a1.y, -a1.y), naz1 = pk2(-a1.z, -a1.z);
    float m0a = 3e38f, m0b = 3e38f, m1a = 3e38f, m1b = 3e38f;
    int colbase = ch * 2048;
    for (int tb = 0; tb < 2048; tb += 256) {
        __syncthreads();
        float4 p0 = B[colbase + tb + 2 * threadIdx.x];
        float4 p1 = B[colbase + tb + 2 * threadIdx.x + 1];
        sA[threadIdx.x] = make_ulonglong2(pk2(p0.x, p1.x), pk2(p0.y, p1.y));
        sB[threadIdx.x] = make_ulonglong2(pk2(p0.z, p1.z), pk2(p0.w, p1.w));
        __syncthreads();
#pragma unroll 4
        for (int j = 0; j < 128; j++) {
            ulonglong2 va = sA[j], vb = sB[j];
            unsigned long long u0 = fma2(nax0, va.x, vb.y);
            u0 = fma2(nay0, va.y, u0);
            u0 = fma2(naz0, vb.x, u0);
            unsigned long long u1 = fma2(nax1, va.x, vb.y);
            u1 = fma2(nay1, va.y, u1);
            u1 = fma2(naz1, vb.x, u1);
            float e0, e1;
            upk2(u0, e0, e1);
            m0a = fminf(m0a, e0); m0b = fminf(m0b, e1);
            upk2(u1, e0, e1);
            m1a = fminf(m1a, e0); m1b = fminf(m1b, e1);
        }
    }
    atomicMin(&g_rowmin[dir][f][r], f2key(fminf(m0a, m0b)));
    atomicMin(&g_rowmin[dir][f][r + 128], f2key(fminf(m1a, m1b)));
}

__global__ void k_final(float* out) {
    __shared__ float sh[32];
    __shared__ double scd[NF];
    int t = threadIdx.x;
    for (int f = 0; f < NF; f++) {
        float acc = 0.f;
        for (int i = t; i < 2 * NSAMP; i += 1024) {
            int dir = i >> 12;
            int r = i & (NSAMP - 1);
            float rmin = key2f(g_rowmin[dir][f][r]);
            float aw = dir ? g_gs[f][r].w : g_ps[f][r].w;
            float w = g_w[f][r];
            float d2 = 2.f * (rmin + aw);
            float d = fminf(sqrtf(fmaxf(d2, 1e-12f)), 1e9f);
            acc += d * w;
        }
        float s = blockReduceSum(acc, sh);
        if (t == 0) scd[f] = (double)s;
        __syncthreads();
    }
    if (t == 0) {
        double wsum = 0.0;
        for (int f = 0; f < NF; f++) wsum += (double)g_mask_frame[f];
        double denom = (wsum > 1.0) ? wsum : 1.0;
        double depth_loss = g_sum_absdiff / denom;
        double normal_loss = g_sum_normal / denom;
        double cds = 0.0, oks = 0.0;
        for (int f = 0; f < NF; f++) {
            double ws = (double)g_wsel[f];
            double dn = (ws > 1.0) ? ws : 1.0;
            if (g_mask_frame[f] >= 10.f) { cds += scd[f] / dn; oks += 1.0; }
        }
        double points_loss = cds / ((oks > 1.0) ? oks : 1.0);
        out[0] = (float)(g_pose_loss + depth_loss + points_loss + normal_loss);
    }
}

// ------------------------- launcher -------------------------
extern "C" void kernel_launch(void* const* d_in, const int* in_sizes, int n_in,
                              void* d_out, int out_size) {
    const float* depth_pred = (const float*)d_in[0];
    const float* points_pred = (const float*)d_in[1];
    const float* depth_gt = (const float*)d_in[2];
    const float* intrinsics = (const float*)d_in[3];
    const float* pose_pred = (const float*)d_in[4];
    const float* pose_gt = (const float*)d_in[5];
    float* out = (float*)d_out;

    k_init<<<128, 256>>>();
    k_pose<<<1, 32>>>(pose_pred, pose_gt);
    k_pass1<<<dim3(HW / 512, NF), 512>>>(depth_pred, depth_gt);
    k_scan1<<<NF, 1024>>>();
    k_pass2<<<dim3(HW / 512, NF), 512>>>();
    k_scan2<<<NF, 1024>>>();
    k_pass3<<<dim3(HW / 512, NF), 512>>>();
    k_scan3<<<NF, 1024>>>();
    k_pixel<<<dim3(HW / 256, NF), 256>>>(depth_pred, depth_gt, intrinsics, points_pred);
    k_chamfer<<<dim3(NSAMP / 256, NF, 4), 128>>>();
    k_final<<<1, 1024>>>(out);
}